// round 9
// baseline (speedup 1.0000x reference)
#include <cuda_runtime.h>

// Geometry (fixed by reference: B=16, C=3, H=W=512)
constexpr int BC   = 48;
constexpr int HW   = 512;
constexpr int L    = HW * HW;        // 262144 px/row (one image == one row)
constexpr int NTOT = BC * L;         // 12,582,912
constexpr int WPL  = HW / 32;        // 16 words per image line
constexpr int WPI  = HW * WPL;       // 8192 words per image
constexpr int NW   = BC * WPI;       // 393,216 mask words

constexpr int WCH  = 1024;           // pixels per warp-chunk
constexpr int NWC  = NTOT / WCH;     // 12288 warp-chunks
constexpr int CPR  = L / WCH;        // 256 warp-chunks per row
constexpr int CHUNK = 8192;          // px per block (loss)
constexpr int NBLK  = NTOT / CHUNK;  // 1536

__device__ float    g_vpos[NTOT];
__device__ float    g_vfp [NTOT];
__device__ float    g_vneg[NTOT];
__device__ unsigned g_tbits[NW];
__device__ unsigned g_xbits[NW];
__device__ unsigned g_abits[NW];
__device__ unsigned long long g_wcnt[NWC];  // packed c0|c1<<21|c2<<42
__device__ int      g_woff0[NWC], g_woff1[NWC], g_woff2[NWC];
__device__ int      g_rcnt0[BC], g_rcnt1[BC], g_rcnt2[BC];
__device__ double   g_sum;
__device__ int      g_cnt;           // zero-initialized; self-resetting ticket

__device__ __forceinline__ float sp_fast(float z) {
    return fmaxf(z, 0.f) + __logf(1.f + __expf(-fabsf(z)));
}

// ---------------- K1: pack t>0 and x>0 bits.
// X read default (L2 prefetch for scatter/loss); T streamed (no L2 retention).
__global__ void k_pack(const float* __restrict__ X, const float* __restrict__ T) {
    int tid = threadIdx.x;
    int p0 = blockIdx.x * 1024 + tid * 4;
    float4 tv = __ldcs((const float4*)(T + p0));
    float4 xv = *(const float4*)(X + p0);
    unsigned tn = (tv.x>0.f) | ((tv.y>0.f)<<1) | ((tv.z>0.f)<<2) | ((tv.w>0.f)<<3);
    unsigned xn = (xv.x>0.f) | ((xv.y>0.f)<<1) | ((xv.z>0.f)<<2) | ((xv.w>0.f)<<3);
    int sh = (tid & 7) * 4;
    unsigned vt = tn << sh, vx = xn << sh;
#pragma unroll
    for (int d = 1; d < 8; d <<= 1) {
        vt |= __shfl_xor_sync(0xffffffffu, vt, d);
        vx |= __shfl_xor_sync(0xffffffffu, vx, d);
    }
    if ((tid & 7) == 0) {
        g_tbits[p0 >> 5] = vt;
        g_xbits[p0 >> 5] = vx;
    }
}

// ---------------- K2: fused aug (7x7 OR) + per-chunk counts + per-row scan.
// One block per image/row. Each warp covers 32 chunks; per chunk, lanes
// compute one aug word each (coalesced), warp-reduce packed counts to smem,
// then the block scans all 256 chunk counts and writes offsets/row totals.
__global__ void k_augscan() {
    int row = blockIdx.x, tid = threadIdx.x;
    int lane = tid & 31, wp = tid >> 5;
    if (row == 0 && tid == 0) g_sum = 0.0;
    __shared__ unsigned long long scnt[CPR];
    const unsigned* base = g_tbits + (row << 13);

    for (int it = 0; it < 32; ++it) {
        int chunk = wp * 32 + it;          // 0..255 within row
        int widx  = chunk * 32 + lane;     // word within image
        int line  = widx >> 4;
        int w     = widx & 15;
        unsigned lo = 0, mid = 0, hi = 0;
        int l0 = line - 3 < 0 ? 0 : line - 3;
        int l1 = line + 3 > HW - 1 ? HW - 1 : line + 3;
        for (int l = l0; l <= l1; ++l) {
            const unsigned* p = base + l * WPL + w;
            mid |= p[0];
            if (w > 0)       lo |= p[-1];
            if (w < WPL - 1) hi |= p[1];
        }
        unsigned out = mid;
#pragma unroll
        for (int s = 1; s <= 3; ++s) {
            out |= __funnelshift_r(mid, hi, s);
            out |= __funnelshift_l(lo, mid, s);
        }
        int gw = (row << 13) + widx;
        g_abits[gw] = out;
        unsigned na = ~out;
        unsigned long long pk = (unsigned long long)__popc(base[widx])
                              | ((unsigned long long)__popc(g_xbits[gw] & na) << 21)
                              | ((unsigned long long)__popc(na) << 42);
#pragma unroll
        for (int d = 16; d; d >>= 1) pk += __shfl_down_sync(0xffffffffu, pk, d);
        if (lane == 0) {
            scnt[chunk] = pk;
            g_wcnt[row * CPR + chunk] = pk;   // scatter reads per-chunk counts
        }
    }
    __syncthreads();

    // block-wide exclusive scan of 256 packed counts
    unsigned long long v = scnt[tid];
    unsigned long long incl = v;
#pragma unroll
    for (int d = 1; d < 32; d <<= 1) {
        unsigned long long t = __shfl_up_sync(0xffffffffu, incl, d);
        if (lane >= d) incl += t;
    }
    __shared__ unsigned long long wt[8];
    if (lane == 31) wt[wp] = incl;
    __syncthreads();
    unsigned long long pre = 0;
    for (int i = 0; i < wp; ++i) pre += wt[i];
    unsigned long long inclT = incl + pre;
    unsigned long long excl = inclT - v;
    const unsigned long long M = 0x1FFFFFull;
    int ci = row * CPR + tid;
    g_woff0[ci] = (int)( excl        & M);
    g_woff1[ci] = (int)((excl >> 21) & M);
    g_woff2[ci] = (int)( excl >> 42);
    if (tid == 255) {
        g_rcnt0[row] = (int)( inclT        & M);
        g_rcnt1[row] = (int)((inclT >> 21) & M);
        g_rcnt2[row] = (int)( inclT >> 42);
    }
}

// ---------------- K3: warp-local ordered scatter (single scan per 1024-px chunk)
__global__ void k_scatter(const float* __restrict__ X) {
    int wp = threadIdx.x >> 5, lane = threadIdx.x & 31;
    int chunk = blockIdx.x * 8 + wp;
    int row = chunk >> 8;
    const unsigned long long M = 0x1FFFFFull;
    unsigned long long pk = g_wcnt[chunk];
    int c1 = (int)((pk >> 21) & M);
    int c2 = (int)(pk >> 42);
    bool useFp = g_rcnt1[row] > 0;      // which of vfp/vneg the loss will read
    bool s1 = useFp && (c1 > 0);
    bool s2 = (!useFp) && (c2 > 0);

    int o0 = g_woff0[chunk];
    float* d0 = g_vpos + row * L;
    int sh = (lane & 7) * 4;
    unsigned below = (1u << sh) - 1u;   // bits strictly below this nibble

    if (!(s1 | s2)) {
        unsigned myw = g_tbits[chunk * 32 + lane];
        int pc = __popc(myw);
        int incl = pc;
#pragma unroll
        for (int d = 1; d < 32; d <<= 1) {
            int t = __shfl_up_sync(0xffffffffu, incl, d);
            if (lane >= d) incl += t;
        }
        int woff = o0 + incl - pc;      // absolute offset of this lane's word
        int pbase = chunk * WCH + lane * 4;
#pragma unroll
        for (int it = 0; it < 8; ++it) {
            int p0 = pbase + it * 128;
            float4 xv = *(const float4*)(X + p0);
            int wsrc = it * 4 + (lane >> 3);
            unsigned wv = __shfl_sync(0xffffffffu, myw,  wsrc);
            int      wo = __shfl_sync(0xffffffffu, woff, wsrc);
            unsigned tn = (wv >> sh) & 0xF;
            int myo = wo + __popc(wv & below);
            float xs[4] = {xv.x, xv.y, xv.z, xv.w};
#pragma unroll
            for (int e = 0; e < 4; ++e) {
                unsigned b = 1u << e;
                if (tn & b) d0[myo + __popc(tn & (b - 1u))] = xs[e];
            }
        }
    } else {
        int o1 = s1 ? g_woff1[chunk] : g_woff2[chunk];
        float* d1 = (s1 ? g_vfp : g_vneg) + row * L;
        int pbase = chunk * WCH + lane * 4;
        for (int it = 0; it < 8; ++it) {
            int p0 = pbase + it * 128;
            float4 xv = *(const float4*)(X + p0);
            int wI = p0 >> 5;
            unsigned tn  = (g_tbits[wI] >> sh) & 0xF;
            unsigned m2n = ((~g_abits[wI]) >> sh) & 0xF;
            unsigned mn;
            if (s1) {
                unsigned xn = (xv.x>0.f) | ((xv.y>0.f)<<1) | ((xv.z>0.f)<<2) | ((xv.w>0.f)<<3);
                mn = xn & m2n;
            } else {
                mn = m2n;
            }
            int pc = __popc(tn) | (__popc(mn) << 16);
            int incl = pc;
#pragma unroll
            for (int d = 1; d < 32; d <<= 1) {
                int t = __shfl_up_sync(0xffffffffu, incl, d);
                if (lane >= d) incl += t;
            }
            int excl = incl - pc;
            int e0 = excl & 0xFFFF, e1 = excl >> 16;
            float xs[4] = {xv.x, xv.y, xv.z, xv.w};
#pragma unroll
            for (int e = 0; e < 4; ++e) {
                unsigned b = 1u << e, ml = b - 1u;
                if (tn & b) d0[o0 + e0 + __popc(tn & ml)] = xs[e];
                if (mn & b) d1[o1 + e1 + __popc(mn & ml)] = xs[e];
            }
            int tot = __shfl_sync(0xffffffffu, incl, 31);
            o0 += tot & 0xFFFF;
            o1 += tot >> 16;
        }
    }
}

// ---------------- K4: fused loss + last-block finalize (X streamed: last reader)
__global__ void k_loss(const float* __restrict__ X, float* __restrict__ out, int n) {
    int blk = blockIdx.x, tid = threadIdx.x;
    int row = blk >> 5, c = blk & 31;
    int cp = g_rcnt0[row], cf = g_rcnt1[row], cn = g_rcnt2[row];
    int cF = cf > 0 ? cf : cn;
    const float* vpos = g_vpos + row * L;
    const float* vF   = (cf > 0 ? g_vfp : g_vneg) + row * L;
    bool gen = (cF > 0);

    int jb = c * CHUNK + tid * 4;
    int mp = 0, st = 0, mf = 0, stf = 0;
    if (cp > 0) { mp = jb % cp; st = 1024 % cp; }
    if (gen)    { mf = jb % cF; stf = 1024 % cF; }

    float acc = 0.f;
    int gbase = blk * CHUNK + tid * 4;
    int sh = (tid & 7) * 4;
    for (int it = 0; it < 8; ++it) {
        int g = gbase + it * 1024;
        float4 xv = __ldcs((const float4*)(X + g));
        unsigned tn = (g_tbits[g >> 5] >> sh) & 0xF;
        float xs[4] = {xv.x, xv.y, xv.z, xv.w};
#pragma unroll
        for (int e = 0; e < 4; ++e) {
            float dp = 5.f;
            if (cp > 0) { int idx = mp + e; idx -= (idx >= cp) ? cp : 0; dp = vpos[idx]; }
            float sim = dp * xs[e];
            acc += sp_fast(sim);
            if (tn & (1u << e)) acc -= sim;
            if (gen) {
                int idx = mf + e; idx -= (idx >= cF) ? cF : 0;
                acc += 0.1f * sp_fast(dp * vF[idx]);
            }
        }
        if (cp > 0) { mp += st;  if (mp >= cp) mp -= cp; }
        if (gen)    { mf += stf; if (mf >= cF) mf -= cF; }
    }

    if (cp > 0) {
        int q = L / cp, rmd = L - q * cp;
        bool fold3 = (cF == 0);
        for (int it = 0; it < 8; ++it) {
            int k0 = c * CHUNK + it * 1024 + tid * 4;
            if (k0 < cp) {
                bool v4 = (k0 + 3 < cp);
                float vv[4];
                if (v4) { float4 t4 = *(const float4*)(vpos + k0);
                          vv[0]=t4.x; vv[1]=t4.y; vv[2]=t4.z; vv[3]=t4.w; }
#pragma unroll
                for (int e = 0; e < 4; ++e) {
                    int k = k0 + e;
                    if (k < cp) {
                        float v = v4 ? vv[e] : vpos[k];
                        float w = (float)(q + (k < rmd ? 1 : 0));
                        float t = sp_fast(v) - v;
                        if (fold3) t += 0.1f * sp_fast(-5.f * v);
                        acc += w * t;
                    }
                }
            }
        }
    } else if (c == 0 && tid == 0) {
        acc += (float)L * (sp_fast(5.f) - 5.f);
        if (cF == 0) acc += 0.1f * (float)L * sp_fast(-25.f);
    }

    __shared__ float shm[8];
    __shared__ bool  last;
    int lane = tid & 31, wp = tid >> 5;
#pragma unroll
    for (int d = 16; d; d >>= 1) acc += __shfl_down_sync(0xffffffffu, acc, d);
    if (lane == 0) shm[wp] = acc;
    __syncthreads();
    if (wp == 0) {
        acc = (lane < 8) ? shm[lane] : 0.f;
#pragma unroll
        for (int d = 4; d; d >>= 1) acc += __shfl_down_sync(0xffffffffu, acc, d);
        if (lane == 0) {
            atomicAdd(&g_sum, (double)acc);
            __threadfence();
            last = (atomicAdd(&g_cnt, 1) == NBLK - 1);
        }
    }
    __syncthreads();
    if (last) {
        __threadfence();
        double s = *(volatile double*)&g_sum;
        float r = (float)(s / (double)NTOT);
        for (int i = tid; i < n; i += 256) out[i] = r;
        if (tid == 0) g_cnt = 0;    // reset for next graph replay
    }
}

extern "C" void kernel_launch(void* const* d_in, const int* in_sizes, int n_in,
                              void* d_out, int out_size) {
    const float* X   = (const float*)d_in[0];
    const float* TGT = (const float*)d_in[1];
    float* out = (float*)d_out;

    k_pack   <<<NTOT / 1024, 256>>>(X, TGT);
    k_augscan<<<BC,          256>>>();
    k_scatter<<<NWC / 8,     256>>>(X);
    k_loss   <<<NBLK,        256>>>(X, out, out_size);
}

// round 13
// speedup vs baseline: 2.5822x; 2.5822x over previous
#include <cuda_runtime.h>

// Geometry (fixed by reference: B=16, C=3, H=W=512)
constexpr int BC   = 48;
constexpr int HW   = 512;
constexpr int L    = HW * HW;        // 262144 px/row
constexpr int NTOT = BC * L;         // 12,582,912
constexpr int WPL  = HW / 32;        // 16 words per image line
constexpr int WPI  = HW * WPL;       // 8192 words per image
constexpr int NW   = BC * WPI;       // 393,216 mask words

constexpr int WCH  = 1024;           // pixels per warp-chunk
constexpr int NWC  = NTOT / WCH;     // 12288 warp-chunks
constexpr int CPR  = L / WCH;        // 256 warp-chunks per row
constexpr int CHUNK = 8192;          // px per block (loss)
constexpr int NBLK  = NTOT / CHUNK;  // 1536

__device__ float    g_vpos[NTOT];
__device__ float    g_vfp [NTOT];
__device__ float    g_vneg[NTOT];
__device__ unsigned g_tbits[NW];
__device__ unsigned g_xbits[NW];
__device__ unsigned g_abits[NW];
__device__ unsigned long long g_wcnt[NWC];  // packed c0|c1<<21|c2<<42
__device__ int      g_rcnt0[BC], g_rcnt1[BC], g_rcnt2[BC];
__device__ double   g_sum;
__device__ int      g_cnt;           // zero-initialized; self-resetting ticket

__device__ __forceinline__ float sp_fast(float z) {
    return fmaxf(z, 0.f) + __logf(1.f + __expf(-fabsf(z)));
}

// ---------------- K1: pack t>0 and x>0 bits.
// X read default (L2 prefetch for scatter/loss); T streamed (no L2 retention).
__global__ void k_pack(const float* __restrict__ X, const float* __restrict__ T) {
    int tid = threadIdx.x;
    if (blockIdx.x == 0 && tid == 0) g_sum = 0.0;   // reset accumulator per replay
    int p0 = blockIdx.x * 1024 + tid * 4;
    float4 tv = __ldcs((const float4*)(T + p0));
    float4 xv = *(const float4*)(X + p0);
    unsigned tn = (tv.x>0.f) | ((tv.y>0.f)<<1) | ((tv.z>0.f)<<2) | ((tv.w>0.f)<<3);
    unsigned xn = (xv.x>0.f) | ((xv.y>0.f)<<1) | ((xv.z>0.f)<<2) | ((xv.w>0.f)<<3);
    int sh = (tid & 7) * 4;
    unsigned vt = tn << sh, vx = xn << sh;
#pragma unroll
    for (int d = 1; d < 8; d <<= 1) {
        vt |= __shfl_xor_sync(0xffffffffu, vt, d);
        vx |= __shfl_xor_sync(0xffffffffu, vx, d);
    }
    if ((tid & 7) == 0) {
        g_tbits[p0 >> 5] = vt;
        g_xbits[p0 >> 5] = vx;
    }
}

// ---------------- K2: aug = clamped 7x7 OR; per-warp-chunk counts via popc
// (full 1536-block grid — parallelism preserved)
__global__ void k_aug() {
    int wi = blockIdx.x * 256 + threadIdx.x;
    int img  = wi >> 13;
    int rem  = wi & (WPI - 1);
    int line = rem >> 4;
    int w    = rem & 15;
    const unsigned* base = g_tbits + (img << 13);
    unsigned lo = 0, mid = 0, hi = 0;
    int l0 = line - 3 < 0 ? 0 : line - 3;
    int l1 = line + 3 > HW - 1 ? HW - 1 : line + 3;
    for (int l = l0; l <= l1; ++l) {
        const unsigned* p = base + l * WPL + w;
        mid |= p[0];
        if (w > 0)       lo |= p[-1];
        if (w < WPL - 1) hi |= p[1];
    }
    unsigned out = mid;
#pragma unroll
    for (int s = 1; s <= 3; ++s) {
        out |= __funnelshift_r(mid, hi, s);
        out |= __funnelshift_l(lo, mid, s);
    }
    g_abits[wi] = out;
    unsigned na = ~out;
    unsigned long long pk = (unsigned long long)__popc(g_tbits[wi])
                          | ((unsigned long long)__popc(g_xbits[wi] & na) << 21)
                          | ((unsigned long long)__popc(na) << 42);
#pragma unroll
    for (int d = 16; d; d >>= 1) pk += __shfl_down_sync(0xffffffffu, pk, d);
    if ((threadIdx.x & 31) == 0) g_wcnt[wi >> 5] = pk;
}

// ---------------- K3: ordered scatter with IN-BLOCK row scan (k_scan fused).
// All 8 chunks of a block lie in one row; the block re-scans that row's 256
// chunk counts locally (2KB from L2, ~25 instr/thread) and keeps offsets in smem.
__global__ void k_scatter(const float* __restrict__ X) {
    int tid = threadIdx.x, lane = tid & 31, wp = tid >> 5;
    int chunk0 = blockIdx.x * 8;
    int row = chunk0 >> 8;
    const unsigned long long M = 0x1FFFFFull;

    // block-wide exclusive scan of the row's 256 packed counts
    unsigned long long v = g_wcnt[row * CPR + tid];
    unsigned long long incl = v;
#pragma unroll
    for (int d = 1; d < 32; d <<= 1) {
        unsigned long long t = __shfl_up_sync(0xffffffffu, incl, d);
        if (lane >= d) incl += t;
    }
    __shared__ unsigned long long wt[8];
    if (lane == 31) wt[wp] = incl;
    __syncthreads();
    unsigned long long pre = 0;
    for (int i = 0; i < wp; ++i) pre += wt[i];
    unsigned long long inclT = incl + pre;
    unsigned long long excl = inclT - v;
    __shared__ int soff0[CPR], soff1[CPR], soff2[CPR];
    __shared__ int src1;
    soff0[tid] = (int)( excl        & M);
    soff1[tid] = (int)((excl >> 21) & M);
    soff2[tid] = (int)( excl >> 42);
    if (tid == 255) {
        int r1 = (int)((inclT >> 21) & M);
        g_rcnt0[row] = (int)( inclT        & M);
        g_rcnt1[row] = r1;
        g_rcnt2[row] = (int)( inclT >> 42);
        src1 = r1;
    }
    __syncthreads();

    int chunk = chunk0 + wp;
    int cl = chunk & 255;
    unsigned long long pk = g_wcnt[chunk];
    int c1 = (int)((pk >> 21) & M);
    int c2 = (int)(pk >> 42);
    bool useFp = src1 > 0;
    bool s1 = useFp && (c1 > 0);
    bool s2 = (!useFp) && (c2 > 0);

    int o0 = soff0[cl];
    float* d0 = g_vpos + row * L;
    int sh = (lane & 7) * 4;
    unsigned below = (1u << sh) - 1u;

    if (!(s1 | s2)) {
        // fast path: positives only, single popc-scan for the whole chunk
        unsigned myw = g_tbits[chunk * 32 + lane];
        int pc = __popc(myw);
        int incl2 = pc;
#pragma unroll
        for (int d = 1; d < 32; d <<= 1) {
            int t = __shfl_up_sync(0xffffffffu, incl2, d);
            if (lane >= d) incl2 += t;
        }
        int woff = o0 + incl2 - pc;
        int pbase = chunk * WCH + lane * 4;
#pragma unroll
        for (int it = 0; it < 8; ++it) {
            int p0 = pbase + it * 128;
            float4 xv = *(const float4*)(X + p0);
            int wsrc = it * 4 + (lane >> 3);
            unsigned wv = __shfl_sync(0xffffffffu, myw,  wsrc);
            int      wo = __shfl_sync(0xffffffffu, woff, wsrc);
            unsigned tn = (wv >> sh) & 0xF;
            int myo = wo + __popc(wv & below);
            float xs[4] = {xv.x, xv.y, xv.z, xv.w};
#pragma unroll
            for (int e = 0; e < 4; ++e) {
                unsigned b = 1u << e;
                if (tn & b) d0[myo + __popc(tn & (b - 1u))] = xs[e];
            }
        }
    } else {
        int o1 = s1 ? soff1[cl] : soff2[cl];
        float* d1 = (s1 ? g_vfp : g_vneg) + row * L;
        int pbase = chunk * WCH + lane * 4;
        for (int it = 0; it < 8; ++it) {
            int p0 = pbase + it * 128;
            float4 xv = *(const float4*)(X + p0);
            int wI = p0 >> 5;
            unsigned tn  = (g_tbits[wI] >> sh) & 0xF;
            unsigned m2n = ((~g_abits[wI]) >> sh) & 0xF;
            unsigned mn;
            if (s1) {
                unsigned xn = (xv.x>0.f) | ((xv.y>0.f)<<1) | ((xv.z>0.f)<<2) | ((xv.w>0.f)<<3);
                mn = xn & m2n;
            } else {
                mn = m2n;
            }
            int pc = __popc(tn) | (__popc(mn) << 16);
            int incl2 = pc;
#pragma unroll
            for (int d = 1; d < 32; d <<= 1) {
                int t = __shfl_up_sync(0xffffffffu, incl2, d);
                if (lane >= d) incl2 += t;
            }
            int excl2 = incl2 - pc;
            int e0 = excl2 & 0xFFFF, e1 = excl2 >> 16;
            float xs[4] = {xv.x, xv.y, xv.z, xv.w};
#pragma unroll
            for (int e = 0; e < 4; ++e) {
                unsigned b = 1u << e, ml = b - 1u;
                if (tn & b) d0[o0 + e0 + __popc(tn & ml)] = xs[e];
                if (mn & b) d1[o1 + e1 + __popc(mn & ml)] = xs[e];
            }
            int tot = __shfl_sync(0xffffffffu, incl2, 31);
            o0 += tot & 0xFFFF;
            o1 += tot >> 16;
        }
    }
}

// ---------------- K4: fused loss + last-block finalize (R8 version, no __ldcs)
__global__ void k_loss(const float* __restrict__ X, float* __restrict__ out, int n) {
    int blk = blockIdx.x, tid = threadIdx.x;
    int row = blk >> 5, c = blk & 31;
    int cp = g_rcnt0[row], cf = g_rcnt1[row], cn = g_rcnt2[row];
    int cF = cf > 0 ? cf : cn;
    const float* vpos = g_vpos + row * L;
    const float* vF   = (cf > 0 ? g_vfp : g_vneg) + row * L;
    bool gen = (cF > 0);

    int jb = c * CHUNK + tid * 4;
    int mp = 0, st = 0, mf = 0, stf = 0;
    if (cp > 0) { mp = jb % cp; st = 1024 % cp; }
    if (gen)    { mf = jb % cF; stf = 1024 % cF; }

    float acc = 0.f;
    int gbase = blk * CHUNK + tid * 4;
    int sh = (tid & 7) * 4;
    for (int it = 0; it < 8; ++it) {
        int g = gbase + it * 1024;
        float4 xv = *(const float4*)(X + g);
        unsigned tn = (g_tbits[g >> 5] >> sh) & 0xF;
        float xs[4] = {xv.x, xv.y, xv.z, xv.w};
#pragma unroll
        for (int e = 0; e < 4; ++e) {
            float dp = 5.f;
            if (cp > 0) { int idx = mp + e; idx -= (idx >= cp) ? cp : 0; dp = vpos[idx]; }
            float sim = dp * xs[e];
            acc += sp_fast(sim);
            if (tn & (1u << e)) acc -= sim;
            if (gen) {
                int idx = mf + e; idx -= (idx >= cF) ? cF : 0;
                acc += 0.1f * sp_fast(dp * vF[idx]);
            }
        }
        if (cp > 0) { mp += st;  if (mp >= cp) mp -= cp; }
        if (gen)    { mf += stf; if (mf >= cF) mf -= cF; }
    }

    if (cp > 0) {
        int q = L / cp, rmd = L - q * cp;
        bool fold3 = (cF == 0);
        for (int it = 0; it < 8; ++it) {
            int k0 = c * CHUNK + it * 1024 + tid * 4;
            if (k0 < cp) {
                bool v4 = (k0 + 3 < cp);
                float vv[4];
                if (v4) { float4 t4 = *(const float4*)(vpos + k0);
                          vv[0]=t4.x; vv[1]=t4.y; vv[2]=t4.z; vv[3]=t4.w; }
#pragma unroll
                for (int e = 0; e < 4; ++e) {
                    int k = k0 + e;
                    if (k < cp) {
                        float v = v4 ? vv[e] : vpos[k];
                        float w = (float)(q + (k < rmd ? 1 : 0));
                        float t = sp_fast(v) - v;
                        if (fold3) t += 0.1f * sp_fast(-5.f * v);
                        acc += w * t;
                    }
                }
            }
        }
    } else if (c == 0 && tid == 0) {
        acc += (float)L * (sp_fast(5.f) - 5.f);
        if (cF == 0) acc += 0.1f * (float)L * sp_fast(-25.f);
    }

    __shared__ float shm[8];
    __shared__ bool  last;
    int lane = tid & 31, wp = tid >> 5;
#pragma unroll
    for (int d = 16; d; d >>= 1) acc += __shfl_down_sync(0xffffffffu, acc, d);
    if (lane == 0) shm[wp] = acc;
    __syncthreads();
    if (wp == 0) {
        acc = (lane < 8) ? shm[lane] : 0.f;
#pragma unroll
        for (int d = 4; d; d >>= 1) acc += __shfl_down_sync(0xffffffffu, acc, d);
        if (lane == 0) {
            atomicAdd(&g_sum, (double)acc);
            __threadfence();
            last = (atomicAdd(&g_cnt, 1) == NBLK - 1);
        }
    }
    __syncthreads();
    if (last) {
        __threadfence();
        double s = *(volatile double*)&g_sum;
        float r = (float)(s / (double)NTOT);
        for (int i = tid; i < n; i += 256) out[i] = r;
        if (tid == 0) g_cnt = 0;    // reset for next graph replay
    }
}

extern "C" void kernel_launch(void* const* d_in, const int* in_sizes, int n_in,
                              void* d_out, int out_size) {
    const float* X   = (const float*)d_in[0];
    const float* TGT = (const float*)d_in[1];
    float* out = (float*)d_out;

    k_pack   <<<NTOT / 1024, 256>>>(X, TGT);
    k_aug    <<<NW / 256,    256>>>();
    k_scatter<<<NWC / 8,     256>>>(X);
    k_loss   <<<NBLK,        256>>>(X, out, out_size);
}

// round 14
// speedup vs baseline: 2.7103x; 1.0496x over previous
#include <cuda_runtime.h>

// Geometry (fixed by reference: B=16, C=3, H=W=512)
constexpr int BC   = 48;
constexpr int HW   = 512;
constexpr int L    = HW * HW;        // 262144 px/row
constexpr int NTOT = BC * L;         // 12,582,912
constexpr int WPL  = HW / 32;        // 16 words per image line
constexpr int WPI  = HW * WPL;       // 8192 words per image
constexpr int NW   = BC * WPI;       // 393,216 mask words

constexpr int WCH  = 1024;           // pixels per warp-chunk
constexpr int NWC  = NTOT / WCH;     // 12288 warp-chunks
constexpr int CPR  = L / WCH;        // 256 warp-chunks per row
constexpr int CHUNK = 8192;          // px per block (loss)
constexpr int NBLK  = NTOT / CHUNK;  // 1536

__device__ float    g_vpos[NTOT];
__device__ float    g_vfp [NTOT];
__device__ float    g_vneg[NTOT];
__device__ unsigned g_tbits[NW];
__device__ unsigned g_xbits[NW];
__device__ unsigned g_abits[NW];
__device__ unsigned long long g_wcnt[NWC];  // packed c0|c1<<21|c2<<42
__device__ int      g_woff0[NWC], g_woff1[NWC], g_woff2[NWC];
__device__ int      g_rcnt0[BC], g_rcnt1[BC], g_rcnt2[BC];
__device__ double   g_sum;
__device__ int      g_cnt;           // zero-initialized; self-resetting ticket

__device__ __forceinline__ float sp_fast(float z) {
    return fmaxf(z, 0.f) + __logf(1.f + __expf(-fabsf(z)));
}

// ---------------- K1: pack t>0 and x>0 bits.
// X read default (L2 prefetch for scatter/loss); T streamed (no L2 retention).
__global__ void k_pack(const float* __restrict__ X, const float* __restrict__ T) {
    int tid = threadIdx.x;
    int p0 = blockIdx.x * 1024 + tid * 4;
    float4 tv = __ldcs((const float4*)(T + p0));
    float4 xv = *(const float4*)(X + p0);
    unsigned tn = (tv.x>0.f) | ((tv.y>0.f)<<1) | ((tv.z>0.f)<<2) | ((tv.w>0.f)<<3);
    unsigned xn = (xv.x>0.f) | ((xv.y>0.f)<<1) | ((xv.z>0.f)<<2) | ((xv.w>0.f)<<3);
    int sh = (tid & 7) * 4;
    unsigned vt = tn << sh, vx = xn << sh;
#pragma unroll
    for (int d = 1; d < 8; d <<= 1) {
        vt |= __shfl_xor_sync(0xffffffffu, vt, d);
        vx |= __shfl_xor_sync(0xffffffffu, vx, d);
    }
    if ((tid & 7) == 0) {
        g_tbits[p0 >> 5] = vt;
        g_xbits[p0 >> 5] = vx;
    }
}

// ---------------- K2: aug = clamped 7x7 OR; per-warp-chunk counts via popc
__global__ void k_aug() {
    int wi = blockIdx.x * 256 + threadIdx.x;
    int img  = wi >> 13;
    int rem  = wi & (WPI - 1);
    int line = rem >> 4;
    int w    = rem & 15;
    const unsigned* base = g_tbits + (img << 13);
    unsigned lo = 0, mid = 0, hi = 0;
    int l0 = line - 3 < 0 ? 0 : line - 3;
    int l1 = line + 3 > HW - 1 ? HW - 1 : line + 3;
    for (int l = l0; l <= l1; ++l) {
        const unsigned* p = base + l * WPL + w;
        mid |= p[0];
        if (w > 0)       lo |= p[-1];
        if (w < WPL - 1) hi |= p[1];
    }
    unsigned out = mid;
#pragma unroll
    for (int s = 1; s <= 3; ++s) {
        out |= __funnelshift_r(mid, hi, s);
        out |= __funnelshift_l(lo, mid, s);
    }
    g_abits[wi] = out;
    unsigned na = ~out;
    unsigned long long pk = (unsigned long long)__popc(g_tbits[wi])
                          | ((unsigned long long)__popc(g_xbits[wi] & na) << 21)
                          | ((unsigned long long)__popc(na) << 42);
#pragma unroll
    for (int d = 16; d; d >>= 1) pk += __shfl_down_sync(0xffffffffu, pk, d);
    if ((threadIdx.x & 31) == 0) g_wcnt[wi >> 5] = pk;
}

// ---------------- K3: per-row exclusive scan of 256 warp-chunk counts (packed)
__global__ void k_scan() {
    int row = blockIdx.x, tid = threadIdx.x;
    if (row == 0 && tid == 0) g_sum = 0.0;
    int lane = tid & 31, wp = tid >> 5;
    unsigned long long v = g_wcnt[row * CPR + tid];
    unsigned long long incl = v;
#pragma unroll
    for (int d = 1; d < 32; d <<= 1) {
        unsigned long long t = __shfl_up_sync(0xffffffffu, incl, d);
        if (lane >= d) incl += t;
    }
    __shared__ unsigned long long wt[8];
    if (lane == 31) wt[wp] = incl;
    __syncthreads();
    unsigned long long pre = 0;
    for (int i = 0; i < wp; ++i) pre += wt[i];
    unsigned long long inclT = incl + pre;
    unsigned long long excl = inclT - v;
    const unsigned long long M = 0x1FFFFFull;
    int ci = row * CPR + tid;
    g_woff0[ci] = (int)( excl        & M);
    g_woff1[ci] = (int)((excl >> 21) & M);
    g_woff2[ci] = (int)( excl >> 42);
    if (tid == 255) {
        g_rcnt0[row] = (int)( inclT        & M);
        g_rcnt1[row] = (int)((inclT >> 21) & M);
        g_rcnt2[row] = (int)( inclT >> 42);
    }
}

// ---------------- K4: warp-local ordered scatter (single scan per 1024-px chunk)
__global__ void k_scatter(const float* __restrict__ X) {
    int wp = threadIdx.x >> 5, lane = threadIdx.x & 31;
    int chunk = blockIdx.x * 8 + wp;
    int row = chunk >> 8;
    const unsigned long long M = 0x1FFFFFull;
    unsigned long long pk = g_wcnt[chunk];
    int c1 = (int)((pk >> 21) & M);
    int c2 = (int)(pk >> 42);
    bool useFp = g_rcnt1[row] > 0;      // which of vfp/vneg the loss will read
    bool s1 = useFp && (c1 > 0);
    bool s2 = (!useFp) && (c2 > 0);

    int o0 = g_woff0[chunk];
    float* d0 = g_vpos + row * L;
    int sh = (lane & 7) * 4;
    unsigned below = (1u << sh) - 1u;   // bits strictly below this nibble

    if (!(s1 | s2)) {
        unsigned myw = g_tbits[chunk * 32 + lane];
        int pc = __popc(myw);
        int incl = pc;
#pragma unroll
        for (int d = 1; d < 32; d <<= 1) {
            int t = __shfl_up_sync(0xffffffffu, incl, d);
            if (lane >= d) incl += t;
        }
        int woff = o0 + incl - pc;      // absolute offset of this lane's word
        int pbase = chunk * WCH + lane * 4;
#pragma unroll
        for (int it = 0; it < 8; ++it) {
            int p0 = pbase + it * 128;
            float4 xv = *(const float4*)(X + p0);
            int wsrc = it * 4 + (lane >> 3);
            unsigned wv = __shfl_sync(0xffffffffu, myw,  wsrc);
            int      wo = __shfl_sync(0xffffffffu, woff, wsrc);
            unsigned tn = (wv >> sh) & 0xF;
            int myo = wo + __popc(wv & below);
            float xs[4] = {xv.x, xv.y, xv.z, xv.w};
#pragma unroll
            for (int e = 0; e < 4; ++e) {
                unsigned b = 1u << e;
                if (tn & b) d0[myo + __popc(tn & (b - 1u))] = xs[e];
            }
        }
    } else {
        int o1 = s1 ? g_woff1[chunk] : g_woff2[chunk];
        float* d1 = (s1 ? g_vfp : g_vneg) + row * L;
        int pbase = chunk * WCH + lane * 4;
        for (int it = 0; it < 8; ++it) {
            int p0 = pbase + it * 128;
            float4 xv = *(const float4*)(X + p0);
            int wI = p0 >> 5;
            unsigned tn  = (g_tbits[wI] >> sh) & 0xF;
            unsigned m2n = ((~g_abits[wI]) >> sh) & 0xF;
            unsigned mn;
            if (s1) {
                unsigned xn = (xv.x>0.f) | ((xv.y>0.f)<<1) | ((xv.z>0.f)<<2) | ((xv.w>0.f)<<3);
                mn = xn & m2n;
            } else {
                mn = m2n;
            }
            int pc = __popc(tn) | (__popc(mn) << 16);
            int incl = pc;
#pragma unroll
            for (int d = 1; d < 32; d <<= 1) {
                int t = __shfl_up_sync(0xffffffffu, incl, d);
                if (lane >= d) incl += t;
            }
            int excl = incl - pc;
            int e0 = excl & 0xFFFF, e1 = excl >> 16;
            float xs[4] = {xv.x, xv.y, xv.z, xv.w};
#pragma unroll
            for (int e = 0; e < 4; ++e) {
                unsigned b = 1u << e, ml = b - 1u;
                if (tn & b) d0[o0 + e0 + __popc(tn & ml)] = xs[e];
                if (mn & b) d1[o1 + e1 + __popc(mn & ml)] = xs[e];
            }
            int tot = __shfl_sync(0xffffffffu, incl, 31);
            o0 += tot & 0xFFFF;
            o1 += tot >> 16;
        }
    }
}

// ---------------- K5: fused loss + last-block finalize.
// Second pass (term2 + folded term3 over vpos[0..cp)) is now partitioned
// EVENLY across the row's 32 blocks — removes the 2:1 block imbalance.
__global__ void k_loss(const float* __restrict__ X, float* __restrict__ out, int n) {
    int blk = blockIdx.x, tid = threadIdx.x;
    int row = blk >> 5, c = blk & 31;
    int cp = g_rcnt0[row], cf = g_rcnt1[row], cn = g_rcnt2[row];
    int cF = cf > 0 ? cf : cn;
    const float* vpos = g_vpos + row * L;
    const float* vF   = (cf > 0 ? g_vfp : g_vneg) + row * L;
    bool gen = (cF > 0);

    int jb = c * CHUNK + tid * 4;
    int mp = 0, st = 0, mf = 0, stf = 0;
    if (cp > 0) { mp = jb % cp; st = 1024 % cp; }
    if (gen)    { mf = jb % cF; stf = 1024 % cF; }

    float acc = 0.f;
    int gbase = blk * CHUNK + tid * 4;
    int sh = (tid & 7) * 4;
    for (int it = 0; it < 8; ++it) {
        int g = gbase + it * 1024;
        float4 xv = *(const float4*)(X + g);
        unsigned tn = (g_tbits[g >> 5] >> sh) & 0xF;
        float xs[4] = {xv.x, xv.y, xv.z, xv.w};
#pragma unroll
        for (int e = 0; e < 4; ++e) {
            float dp = 5.f;
            if (cp > 0) { int idx = mp + e; idx -= (idx >= cp) ? cp : 0; dp = vpos[idx]; }
            float sim = dp * xs[e];
            acc += sp_fast(sim);
            if (tn & (1u << e)) acc -= sim;
            if (gen) {
                int idx = mf + e; idx -= (idx >= cF) ? cF : 0;
                acc += 0.1f * sp_fast(dp * vF[idx]);
            }
        }
        if (cp > 0) { mp += st;  if (mp >= cp) mp -= cp; }
        if (gen)    { mf += stf; if (mf >= cF) mf -= cF; }
    }

    if (cp > 0) {
        int q = L / cp, rmd = L - q * cp;
        bool fold3 = (cF == 0);
        // balanced partition: this block covers k in [cp*c/32, cp*(c+1)/32)
        int start = (int)(((long long)cp * c) >> 5);
        int end   = (int)(((long long)cp * (c + 1)) >> 5);
        for (int k = start + tid; k < end; k += 256) {
            float v = vpos[k];
            float w = (float)(q + (k < rmd ? 1 : 0));
            float t = sp_fast(v) - v;
            if (fold3) t += 0.1f * sp_fast(-5.f * v);
            acc += w * t;
        }
    } else if (c == 0 && tid == 0) {
        acc += (float)L * (sp_fast(5.f) - 5.f);
        if (cF == 0) acc += 0.1f * (float)L * sp_fast(-25.f);
    }

    __shared__ float shm[8];
    __shared__ bool  last;
    int lane = tid & 31, wp = tid >> 5;
#pragma unroll
    for (int d = 16; d; d >>= 1) acc += __shfl_down_sync(0xffffffffu, acc, d);
    if (lane == 0) shm[wp] = acc;
    __syncthreads();
    if (wp == 0) {
        acc = (lane < 8) ? shm[lane] : 0.f;
#pragma unroll
        for (int d = 4; d; d >>= 1) acc += __shfl_down_sync(0xffffffffu, acc, d);
        if (lane == 0) {
            atomicAdd(&g_sum, (double)acc);
            __threadfence();
            last = (atomicAdd(&g_cnt, 1) == NBLK - 1);
        }
    }
    __syncthreads();
    if (last) {
        __threadfence();
        double s = *(volatile double*)&g_sum;
        float r = (float)(s / (double)NTOT);
        for (int i = tid; i < n; i += 256) out[i] = r;
        if (tid == 0) g_cnt = 0;    // reset for next graph replay
    }
}

extern "C" void kernel_launch(void* const* d_in, const int* in_sizes, int n_in,
                              void* d_out, int out_size) {
    const float* X   = (const float*)d_in[0];
    const float* TGT = (const float*)d_in[1];
    float* out = (float*)d_out;

    k_pack   <<<NTOT / 1024, 256>>>(X, TGT);
    k_aug    <<<NW / 256,    256>>>();
    k_scan   <<<BC,          256>>>();
    k_scatter<<<NWC / 8,     256>>>(X);
    k_loss   <<<NBLK,        256>>>(X, out, out_size);
}